// round 13
// baseline (speedup 1.0000x reference)
#include <cuda_runtime.h>
#include <cuda_fp16.h>
#include <cstdint>

#define NE 16
#define DIN 128
#define HID 512
#define DOUT 64
#define BATCH 8192

// ---------------- device scratch (16B aligned for cp.async) ----------------
__device__ __align__(16) __half g_W1h[NE * HID * DIN];
__device__ __align__(16) __half g_W1l[NE * HID * DIN];
__device__ __align__(16) __half g_W2h[NE * HID * HID];
__device__ __align__(16) __half g_W2l[NE * HID * HID];
__device__ __align__(16) __half g_W3h[NE * DOUT * HID];
__device__ __align__(16) __half g_W3l[NE * DOUT * HID];
__device__ float g_part[(size_t)NE * BATCH * DOUT];

// ---------------- smem map (bytes) ----------------
#define SM_XH   0        // X / h2 hi: 64 x 136 halves (272B stride)
#define SM_XL   17408
#define SM_BUF  34816    // 3 weight buffers, each 18432 (hi 9216 + lo 9216)
#define BUF_SZ  18432
#define SM_H1H  90112    // h1 hi: 64 x 520 halves (1040B stride)
#define SM_H1L  156672
#define SMEM_SZ 223232

__device__ __forceinline__ uint32_t smem_u32(const void* p) {
    uint32_t a;
    asm("{ .reg .u64 t; cvta.to.shared.u64 t, %1; cvt.u32.u64 %0, t; }" : "=r"(a) : "l"(p));
    return a;
}
#define CP_COMMIT asm volatile("cp.async.commit_group;" ::: "memory")
#define CP_WAIT1  asm volatile("cp.async.wait_group 1;" ::: "memory")

#define LDSM_X4(r0, r1, r2, r3, addr) \
    asm volatile("ldmatrix.sync.aligned.m8n8.x4.shared.b16 {%0,%1,%2,%3}, [%4];" \
        : "=r"(r0), "=r"(r1), "=r"(r2), "=r"(r3) : "r"(addr))

__device__ __forceinline__ void mma16816(float* c, uint32_t a0, uint32_t a1, uint32_t a2,
                                         uint32_t a3, uint32_t b0, uint32_t b1) {
    asm volatile(
        "mma.sync.aligned.m16n8k16.row.col.f32.f16.f16.f32 "
        "{%0,%1,%2,%3},{%4,%5,%6,%7},{%8,%9},{%0,%1,%2,%3};"
        : "+f"(c[0]), "+f"(c[1]), "+f"(c[2]), "+f"(c[3])
        : "r"(a0), "r"(a1), "r"(a2), "r"(a3), "r"(b0), "r"(b1));
}

// ---------------- panel source schedule (64n x 64k panels) ----------------
struct Src { const __half* h; const __half* l; int stride; };

__device__ __forceinline__ Src panel_src(int e, int P) {
    Src s;
    if (P < 16) {
        int nc = P >> 1, hf = P & 1;
        size_t o = ((size_t)e * HID + nc * 64) * DIN + hf * 64;
        s.h = g_W1h + o; s.l = g_W1l + o; s.stride = DIN;
        return s;
    }
    int Q = P - 16, nc = Q / 9, j = Q - nc * 9;
    if (j < 8) {
        size_t o = ((size_t)e * HID + nc * 64) * HID + j * 64;
        s.h = g_W2h + o; s.l = g_W2l + o; s.stride = HID;
        return s;
    }
    size_t o = (size_t)e * DOUT * HID + nc * 64;
    s.h = g_W3h + o; s.l = g_W3l + o; s.stride = HID;
    return s;
}

// load one weight panel [64n x 64k] hi+lo into a buffer (row stride 144 B), 256 thr
__device__ __forceinline__ void load_panel(uint32_t sb, uint32_t buf, Src s, int tid) {
#pragma unroll
    for (int i = 0; i < 2; i++) {
        int idx = tid + i * 256;                 // 0..511
        int r = idx >> 3, j = idx & 7;
        uint32_t d = sb + buf + r * 144 + j * 16;
        const __half* pH = s.h + (size_t)r * s.stride + j * 8;
        const __half* pL = s.l + (size_t)r * s.stride + j * 8;
        asm volatile("cp.async.cg.shared.global [%0], [%1], 16;" :: "r"(d), "l"(pH));
        asm volatile("cp.async.cg.shared.global [%0], [%1], 16;" :: "r"(d + 4608 * 2), "l"(pL));
    }
}

// K=64 panel via ldmatrix: warp tile 16m x 32n, 3-term Ah*Wh + Al*Wh + Ah*Wl.
// aAddr: lane-resolved ldmatrix address for A-hi (lane%16 rows, lane/16 k-halves)
// b0a/b1a: lane-resolved addresses for the warp's two 16-row B blocks (hi; lo at +9216)
__device__ __forceinline__ void gemm_lm(uint32_t aAddr, uint32_t aLod,
                                        uint32_t b0a, uint32_t b1a, float* acc) {
#pragma unroll
    for (int k16 = 0; k16 < 4; k16++) {
        const uint32_t ko = k16 * 32;
        uint32_t a0, a1, a2, a3, l0, l1, l2, l3;
        LDSM_X4(a0, a1, a2, a3, aAddr + ko);
        LDSM_X4(l0, l1, l2, l3, aAddr + aLod + ko);
        uint32_t p0, p1, p2, p3, q0, q1, q2, q3;
        LDSM_X4(p0, p1, p2, p3, b0a + ko);          // hi, nb 0-1
        LDSM_X4(q0, q1, q2, q3, b1a + ko);          // hi, nb 2-3
        uint32_t u0, u1, u2, u3, v0, v1, v2, v3;
        LDSM_X4(u0, u1, u2, u3, b0a + 9216 + ko);   // lo, nb 0-1
        LDSM_X4(v0, v1, v2, v3, b1a + 9216 + ko);   // lo, nb 2-3
        mma16816(acc + 0,  a0, a1, a2, a3, p0, p1);
        mma16816(acc + 0,  l0, l1, l2, l3, p0, p1);
        mma16816(acc + 0,  a0, a1, a2, a3, u0, u1);
        mma16816(acc + 4,  a0, a1, a2, a3, p2, p3);
        mma16816(acc + 4,  l0, l1, l2, l3, p2, p3);
        mma16816(acc + 4,  a0, a1, a2, a3, u2, u3);
        mma16816(acc + 8,  a0, a1, a2, a3, q0, q1);
        mma16816(acc + 8,  l0, l1, l2, l3, q0, q1);
        mma16816(acc + 8,  a0, a1, a2, a3, v0, v1);
        mma16816(acc + 12, a0, a1, a2, a3, q2, q3);
        mma16816(acc + 12, l0, l1, l2, l3, q2, q3);
        mma16816(acc + 12, a0, a1, a2, a3, v2, v3);
    }
}

__device__ __forceinline__ void split_st(char* sm, uint32_t oh, int lod, float v0, float v1) {
    __half h0 = __float2half_rn(v0), h1 = __float2half_rn(v1);
    __half l0 = __float2half_rn(v0 - __half2float(h0));
    __half l1 = __float2half_rn(v1 - __half2float(h1));
    *(__half2*)(sm + oh) = __halves2half2(h0, h1);
    *(__half2*)(sm + oh + lod) = __halves2half2(l0, l1);
}

// relu(acc+bias) -> hi/lo fp16, warp tile 16x32 (rows r0, r0+8)
__device__ __forceinline__ void epi_relu(char* sm, uint32_t dstH, int lod, int strB,
                                         const float* __restrict__ bias, const float* acc,
                                         int r0, int cw) {
#pragma unroll
    for (int nb = 0; nb < 4; nb++) {
        const float* c = acc + nb * 4;
        int cc = cw + nb * 8;
        float bz0 = __ldg(bias + cc), bz1 = __ldg(bias + cc + 1);
        float v00 = fmaxf(c[0] + bz0, 0.f);
        float v01 = fmaxf(c[1] + bz1, 0.f);
        float v10 = fmaxf(c[2] + bz0, 0.f);
        float v11 = fmaxf(c[3] + bz1, 0.f);
        split_st(sm, dstH + r0 * strB + cc * 2, lod, v00, v01);
        split_st(sm, dstH + (r0 + 8) * strB + cc * 2, lod, v10, v11);
    }
}

// ---------------- prologue: transpose + fp16 hi/lo split ----------------
__global__ void tsplit(const float* __restrict__ src, int which, int K, int N) {
    __shared__ float t[32][33];
    __half *dh, *dl;
    if (which == 0) { dh = g_W1h; dl = g_W1l; }
    else if (which == 1) { dh = g_W2h; dl = g_W2l; }
    else { dh = g_W3h; dl = g_W3l; }
    int e = blockIdx.z, k0 = blockIdx.x * 32, n0 = blockIdx.y * 32;
    int tx = threadIdx.x, ty = threadIdx.y;
    const float* s = src + (size_t)e * K * N;
#pragma unroll
    for (int i = 0; i < 32; i += 8)
        t[ty + i][tx] = s[(size_t)(k0 + ty + i) * N + n0 + tx];
    __syncthreads();
#pragma unroll
    for (int i = 0; i < 32; i += 8) {
        float v = t[tx][ty + i];
        __half h = __float2half_rn(v);
        size_t o = (size_t)e * N * K + (size_t)(n0 + ty + i) * K + k0 + tx;
        dh[o] = h;
        dl[o] = __float2half_rn(v - __half2float(h));
    }
}

// ---------------- main fused kernel: 256 thr, 8 warps, ldmatrix fragments ----------------
__global__ void __launch_bounds__(256, 1)
moe_main(const float* __restrict__ x, const float* __restrict__ b1,
         const float* __restrict__ b2, const float* __restrict__ b3) {
    extern __shared__ char sm[];
    const int tid = threadIdx.x, wid = tid >> 5, lid = tid & 31;
    const int g = lid >> 2, t = lid & 3;
    const int wR = wid & 3, wC = wid >> 2;
    const int m0 = blockIdx.x * 64, e = blockIdx.y;
    const uint32_t sb = smem_u32(sm);

    // prefetch panels 0,1 (overlap with X conversion)
    load_panel(sb, SM_BUF + 0 * BUF_SZ, panel_src(e, 0), tid); CP_COMMIT;
    load_panel(sb, SM_BUF + 1 * BUF_SZ, panel_src(e, 1), tid); CP_COMMIT;

    // X tile [64 x 128] -> fp16 hi/lo, row stride 136 halves (272 B)
    for (int i = tid; i < 2048; i += 256) {
        int r = i >> 5, j = i & 31;
        float4 f = ((const float4*)(x + ((size_t)(m0 + r) * NE + e) * DIN))[j];
        uint32_t o = (uint32_t)(r * 136 + j * 4) * 2;
        split_st(sm, SM_XH + o, SM_XL - SM_XH, f.x, f.y);
        split_st(sm, SM_XH + o + 4, SM_XL - SM_XH, f.z, f.w);
    }
    __syncthreads();   // X visible

    // ---- lane-resolved ldmatrix addresses ----
    const int lrow = lid & 15, lk = lid >> 4;            // A: row, k-half
    const int nrow = (lid & 7) + ((lid & 16) >> 1);      // B: row within 16-block
    const int bko  = (lid & 8) ? 16 : 0;                 // B: k-byte offset
    const int mrow = wR * 16 + g, cw = wC * 32 + t * 2;

    const uint32_t aX  = sb + SM_XH  + (uint32_t)((wR * 16 + lrow) * 272 + lk * 16);
    const uint32_t aH1 = sb + SM_H1H + (uint32_t)((wR * 16 + lrow) * 1040 + lk * 16);
    const uint32_t aH2 = sb + SM_XH  + (uint32_t)((wR * 16 + lrow) * 144 + lk * 16);
    const uint32_t bL0 = (uint32_t)((wC * 32 + nrow) * 144 + bko);
    const uint32_t bL1 = bL0 + 16 * 144;
    const float* b1e = b1 + e * HID;
    const float* b2e = b2 + e * HID;
    const float* b3e = b3 + e * DOUT;

    float acc[16], out[16];
#pragma unroll
    for (int i = 0; i < 16; i++) { acc[i] = 0.f; out[i] = 0.f; }

    // ---- flat 88-panel pipeline ----
    for (int P = 0; P < 88; ++P) {
        CP_WAIT1;
        __syncthreads();
        if (P + 2 < 88)
            load_panel(sb, SM_BUF + ((P + 2) % 3) * BUF_SZ, panel_src(e, P + 2), tid);
        CP_COMMIT;
        const uint32_t bufP = sb + SM_BUF + (P % 3) * BUF_SZ;

        if (P < 16) {
            gemm_lm(aX + (P & 1) * 128, SM_XL - SM_XH, bufP + bL0, bufP + bL1, acc);
            if (P & 1) {
                int nc = P >> 1;
                epi_relu(sm, SM_H1H + nc * 128, SM_H1L - SM_H1H, 1040,
                         b1e + nc * 64, acc, mrow, cw);
#pragma unroll
                for (int i = 0; i < 16; i++) acc[i] = 0.f;
            }
            if (P == 15) __syncthreads();   // h1 complete
        } else {
            int Q = P - 16, nc = Q / 9, j = Q - nc * 9;
            if (j < 8) {
                gemm_lm(aH1 + j * 128, SM_H1L - SM_H1H, bufP + bL0, bufP + bL1, acc);
                if (j == 7) {
                    epi_relu(sm, SM_XH, SM_XL - SM_XH, 144, b2e + nc * 64, acc, mrow, cw);
#pragma unroll
                    for (int i = 0; i < 16; i++) acc[i] = 0.f;
                    __syncthreads();        // h2 visible before W3 panel
                }
            } else {
                gemm_lm(aH2, SM_XL - SM_XH, bufP + bL0, bufP + bL1, out);
                __syncthreads();            // h2 reads done before next chunk epi
            }
        }
    }

    // ---- write partial [e][m][64] ----
    float* dst = g_part + ((size_t)e * BATCH + m0) * DOUT;
#pragma unroll
    for (int nb = 0; nb < 4; nb++) {
        const float* c = out + nb * 4;
        int cc = cw + nb * 8;
        float bz0 = __ldg(b3e + cc), bz1 = __ldg(b3e + cc + 1);
        *(float2*)(dst + (size_t)mrow * DOUT + cc) = make_float2(c[0] + bz0, c[1] + bz1);
        *(float2*)(dst + (size_t)(mrow + 8) * DOUT + cc) = make_float2(c[2] + bz0, c[3] + bz1);
    }
}

// ---------------- deterministic expert reduction ----------------
__global__ void reduce_out(float* __restrict__ out) {
    int i = blockIdx.x * blockDim.x + threadIdx.x;
    float s = 0.f;
#pragma unroll
    for (int e = 0; e < NE; e++) s += g_part[(size_t)e * BATCH * DOUT + i];
    out[i] = s;
}

// ---------------- launcher ----------------
extern "C" void kernel_launch(void* const* d_in, const int* in_sizes, int n_in,
                              void* d_out, int out_size) {
    const float* x  = (const float*)d_in[0];
    const float* W1 = (const float*)d_in[1];
    const float* b1 = (const float*)d_in[2];
    const float* W2 = (const float*)d_in[3];
    const float* b2 = (const float*)d_in[4];
    const float* W3 = (const float*)d_in[5];
    const float* b3 = (const float*)d_in[6];
    float* out = (float*)d_out;

    cudaFuncSetAttribute(moe_main, cudaFuncAttributeMaxDynamicSharedMemorySize, SMEM_SZ);

    dim3 t32(32, 8);
    tsplit<<<dim3(DIN / 32, HID / 32, NE), t32>>>(W1, 0, DIN, HID);
    tsplit<<<dim3(HID / 32, HID / 32, NE), t32>>>(W2, 1, HID, HID);
    tsplit<<<dim3(HID / 32, DOUT / 32, NE), t32>>>(W3, 2, HID, DOUT);

    moe_main<<<dim3(BATCH / 64, NE), 256, SMEM_SZ>>>(x, b1, b2, b3);

    reduce_out<<<(BATCH * DOUT) / 256, 256>>>(out);
}